// round 10
// baseline (speedup 1.0000x reference)
#include <cuda_runtime.h>
#include <stdint.h>

#define BATCH   8
#define SEQ     2048
#define EMBED   1024
#define HEAD    128
#define MROWS   16384
#define TQ      16

// Scratch — __device__ globals, no alloc.
__device__ float g_pO[2 * MROWS * HEAD];
__device__ float g_pm[2 * MROWS];
__device__ float g_pl[2 * MROWS];
// K/V projections, fp32 values pre-rounded to tf32
__device__ __align__(16) float g_K[MROWS * HEAD];
__device__ __align__(16) float g_V[MROWS * HEAD];
// W transposed, tf32-rounded: [(m*128+n)][k]  (m: 0=K, 1=V)
__device__ __align__(16) float g_wt[2 * HEAD * EMBED];

// ---------------------------------------------------------------------------
__device__ __forceinline__ uint32_t cvt_tf32(float f) {
    uint32_t r;
    asm("cvt.rna.tf32.f32 %0, %1;" : "=r"(r) : "f"(f));
    return r;
}
__device__ __forceinline__ void mma_tf32(float* c, const uint32_t* a, const uint32_t* b) {
    asm volatile(
        "mma.sync.aligned.m16n8k8.row.col.f32.tf32.tf32.f32 "
        "{%0,%1,%2,%3}, {%4,%5,%6,%7}, {%8,%9}, {%0,%1,%2,%3};"
        : "+f"(c[0]), "+f"(c[1]), "+f"(c[2]), "+f"(c[3])
        : "r"(a[0]), "r"(a[1]), "r"(a[2]), "r"(a[3]), "r"(b[0]), "r"(b[1]));
}

// ---------------------------------------------------------------------------
// W prep: transpose + tf32 rounding. Wk/Wv are [1024][128].
// ---------------------------------------------------------------------------
__global__ __launch_bounds__(256) void wprep_kernel(
    const float* __restrict__ Wk, const float* __restrict__ Wv)
{
    int idx = blockIdx.x * 256 + threadIdx.x;
    int n = idx & 127;
    int k = (idx >> 7) & 1023;
    int m = idx >> 17;
    float f = (m ? Wv : Wk)[k * HEAD + n];
    g_wt[(size_t)(m * HEAD + n) * EMBED + k] = __uint_as_float(cvt_tf32(f));
}

// ---------------------------------------------------------------------------
// Projection GEMM via mma.sync tf32 (single product).
// CTA tile 128x128, 8 warps (2x4), warp tile 64x32, k chunked by 64.
// grid (128, 2).
// ---------------------------------------------------------------------------
#define PJSTR 68
#define PROJ_SMEM (2 * 128 * PJSTR * 4)   // 69632

__global__ __launch_bounds__(256, 2) void proj_mma_kernel(const float* __restrict__ x)
{
    extern __shared__ float psm[];
    float* As = psm;                  // [128][68]
    float* Bs = psm + 128 * PJSTR;    // [128][68]

    const int bm  = blockIdx.x;
    const int bn  = blockIdx.y;
    const int tid = threadIdx.x;
    const int wid = tid >> 5;
    const int lane = tid & 31;
    const int g = lane >> 2;
    const int t = lane & 3;

    const int warp_m = (wid >> 2) * 64;
    const int warp_n = (wid & 3) * 32;

    const int r = tid >> 1;
    const int h = tid & 1;
    const float* xrow = x + (size_t)(bm * 128 + r) * EMBED;
    const float* wrow = g_wt + (size_t)(bn * 128 + r) * EMBED;

    float acc[4][4][4] = {};

    for (int c = 0; c < 16; c++) {
        const int k0 = c * 64;
        __syncthreads();
        // A: load x fp32, round to tf32, store
        #pragma unroll
        for (int j = 0; j < 8; j++) {
            float4 f = *(const float4*)&xrow[k0 + h * 32 + j * 4];
            float4 o;
            o.x = __uint_as_float(cvt_tf32(f.x));
            o.y = __uint_as_float(cvt_tf32(f.y));
            o.z = __uint_as_float(cvt_tf32(f.z));
            o.w = __uint_as_float(cvt_tf32(f.w));
            *(float4*)&As[r * PJSTR + h * 32 + j * 4] = o;
        }
        // B: already rounded — plain copy
        #pragma unroll
        for (int j = 0; j < 8; j++)
            *(float4*)&Bs[r * PJSTR + h * 32 + j * 4] =
                *(const float4*)&wrow[k0 + h * 32 + j * 4];
        __syncthreads();

        #pragma unroll
        for (int kk = 0; kk < 8; kk++) {
            uint32_t a[4][4];
            #pragma unroll
            for (int mf = 0; mf < 4; mf++) {
                int ab = (warp_m + mf * 16 + g) * PJSTR + kk * 8 + t;
                a[mf][0] = __float_as_uint(As[ab]);
                a[mf][1] = __float_as_uint(As[ab + 8 * PJSTR]);
                a[mf][2] = __float_as_uint(As[ab + 4]);
                a[mf][3] = __float_as_uint(As[ab + 8 * PJSTR + 4]);
            }
            #pragma unroll
            for (int nf = 0; nf < 4; nf++) {
                int bb = (warp_n + nf * 8 + g) * PJSTR + kk * 8 + t;
                uint32_t b[2];
                b[0] = __float_as_uint(Bs[bb]);
                b[1] = __float_as_uint(Bs[bb + 4]);
                #pragma unroll
                for (int mf = 0; mf < 4; mf++)
                    mma_tf32(acc[mf][nf], a[mf], b);
            }
        }
    }

    // epilogue: tf32-round and store fp32
    float* dst = (bn ? g_V : g_K) + (size_t)bm * 128 * HEAD;
    const int frow = lane >> 2;
    const int fc2  = (lane & 3) * 2;
    #pragma unroll
    for (int mf = 0; mf < 4; mf++) {
        #pragma unroll
        for (int nf = 0; nf < 4; nf++) {
            int row0 = warp_m + mf * 16 + frow;
            int col  = warp_n + nf * 8 + fc2;
            float2 v0 = make_float2(__uint_as_float(cvt_tf32(acc[mf][nf][0])),
                                    __uint_as_float(cvt_tf32(acc[mf][nf][1])));
            float2 v1 = make_float2(__uint_as_float(cvt_tf32(acc[mf][nf][2])),
                                    __uint_as_float(cvt_tf32(acc[mf][nf][3])));
            *(float2*)&dst[(size_t)row0 * HEAD + col]       = v0;
            *(float2*)&dst[(size_t)(row0 + 8) * HEAD + col] = v1;
        }
    }
}

// ---------------------------------------------------------------------------
// Flash-attention partial via mma.sync tf32 (single product).
// BQ=BK=128, 8 warps x 16 q-rows, register-resident softmax.
// grid = 256 1-D blocks: (qi, b, half) split-K schedule, big tiles first.
// ---------------------------------------------------------------------------
#define QSTR 132
#define ATTN_SMEM (2 * 128 * QSTR * 4)   // 135168

__global__ __launch_bounds__(256, 1) void attn_partial(void)
{
    const int tt   = blockIdx.x;
    const int qi   = (TQ - 1) - (tt >> 4);
    const int b    = (tt >> 1) & 7;
    const int half = tt & 1;
    const int hm   = (qi + 1) >> 1;
    const int jbeg = half ? hm : 0;
    const int jend = half ? (qi + 1) : hm;

    const int tid  = threadIdx.x;
    const int wid  = tid >> 5;
    const int lane = tid & 31;
    const int g = lane >> 2;
    const int t = lane & 3;

    const size_t prow0 = (size_t)half * MROWS + (size_t)b * SEQ + qi * 128;
    const size_t pbase = prow0 * HEAD;

    if (jbeg == jend) {
        float4 z = make_float4(0.f, 0.f, 0.f, 0.f);
        #pragma unroll
        for (int i = 0; i < 16; i++)
            *(float4*)&g_pO[pbase + (size_t)(wid * 16 + i) * HEAD + lane * 4] = z;
        if (tid < 128) { g_pm[prow0 + tid] = -1e30f; g_pl[prow0 + tid] = 0.0f; }
        return;
    }

    extern __shared__ float asm_[];
    float* Qs  = asm_;                 // [128][132]
    float* KVs = asm_ + 128 * QSTR;    // [128][132]  K tile, then V tile

    const int cr = tid >> 1;
    const int ch = tid & 1;
    const size_t batch0 = (size_t)b * SEQ;

    // --- load Q tile (q = key(x): from g_K) ---
    {
        const float* src = g_K + (batch0 + qi * 128 + cr) * HEAD + ch * 64;
        #pragma unroll
        for (int i = 0; i < 16; i++)
            *(float4*)&Qs[cr * QSTR + ch * 64 + i * 4] = *(const float4*)&src[i * 4];
    }

    const int warp_m = wid * 16;
    const int frow = g;
    const int fc2  = t * 2;

    float o[16][4] = {};
    float m0 = -1e30f, m1 = -1e30f, l0 = 0.f, l1 = 0.f;
    const float sc = 0.08838834764831845f;

    for (int j = jbeg; j < jend; j++) {
        __syncthreads();   // KV buffer free
        // --- load K tile ---
        {
            const float* src = g_K + (batch0 + j * 128 + cr) * HEAD + ch * 64;
            #pragma unroll
            for (int i = 0; i < 16; i++)
                *(float4*)&KVs[cr * QSTR + ch * 64 + i * 4] = *(const float4*)&src[i * 4];
        }
        __syncthreads();

        // --- S = Q K^T ---
        float s[16][4];
        #pragma unroll
        for (int nf = 0; nf < 16; nf++)
            #pragma unroll
            for (int c = 0; c < 4; c++) s[nf][c] = 0.f;

        #pragma unroll 1
        for (int ks = 0; ks < 16; ks++) {
            uint32_t a[4];
            int ab = (warp_m + g) * QSTR + ks * 8 + t;
            a[0] = __float_as_uint(Qs[ab]);
            a[1] = __float_as_uint(Qs[ab + 8 * QSTR]);
            a[2] = __float_as_uint(Qs[ab + 4]);
            a[3] = __float_as_uint(Qs[ab + 8 * QSTR + 4]);
            #pragma unroll
            for (int nf = 0; nf < 16; nf++) {
                int bb = (nf * 8 + g) * QSTR + ks * 8 + t;
                uint32_t bfr[2];
                bfr[0] = __float_as_uint(KVs[bb]);
                bfr[1] = __float_as_uint(KVs[bb + 4]);
                mma_tf32(s[nf], a, bfr);
            }
        }
        __syncthreads();   // all warps done reading K

        // --- load V tile into KV (overlaps softmax) ---
        {
            const float* src = g_V + (batch0 + j * 128 + cr) * HEAD + ch * 64;
            #pragma unroll
            for (int i = 0; i < 16; i++)
                *(float4*)&KVs[cr * QSTR + ch * 64 + i * 4] = *(const float4*)&src[i * 4];
        }

        // --- softmax (registers only) ---
        #pragma unroll
        for (int nf = 0; nf < 16; nf++)
            #pragma unroll
            for (int c = 0; c < 4; c++) s[nf][c] *= sc;

        if (j == qi) {
            #pragma unroll
            for (int nf = 0; nf < 16; nf++) {
                int c0 = nf * 8 + fc2;
                int r0 = warp_m + frow;
                if (c0 > r0)         s[nf][0] = -1e30f;
                if (c0 + 1 > r0)     s[nf][1] = -1e30f;
                if (c0 > r0 + 8)     s[nf][2] = -1e30f;
                if (c0 + 1 > r0 + 8) s[nf][3] = -1e30f;
            }
        }

        float mx0 = -1e30f, mx1 = -1e30f;
        #pragma unroll
        for (int nf = 0; nf < 16; nf++) {
            mx0 = fmaxf(mx0, fmaxf(s[nf][0], s[nf][1]));
            mx1 = fmaxf(mx1, fmaxf(s[nf][2], s[nf][3]));
        }
        mx0 = fmaxf(mx0, __shfl_xor_sync(0xFFFFFFFFu, mx0, 1));
        mx0 = fmaxf(mx0, __shfl_xor_sync(0xFFFFFFFFu, mx0, 2));
        mx1 = fmaxf(mx1, __shfl_xor_sync(0xFFFFFFFFu, mx1, 1));
        mx1 = fmaxf(mx1, __shfl_xor_sync(0xFFFFFFFFu, mx1, 2));

        float mn0 = fmaxf(m0, mx0);
        float mn1 = fmaxf(m1, mx1);
        float e0 = __expf(m0 - mn0);
        float e1 = __expf(m1 - mn1);
        m0 = mn0; m1 = mn1;

        uint32_t p[16][4];
        float sum0 = 0.f, sum1 = 0.f;
        #pragma unroll
        for (int nf = 0; nf < 16; nf++) {
            float p0 = __expf(s[nf][0] - mn0);
            float p1 = __expf(s[nf][1] - mn0);
            float p2 = __expf(s[nf][2] - mn1);
            float p3 = __expf(s[nf][3] - mn1);
            sum0 += p0 + p1;
            sum1 += p2 + p3;
            p[nf][0] = cvt_tf32(p0);
            p[nf][1] = cvt_tf32(p1);
            p[nf][2] = cvt_tf32(p2);
            p[nf][3] = cvt_tf32(p3);
        }
        sum0 += __shfl_xor_sync(0xFFFFFFFFu, sum0, 1);
        sum0 += __shfl_xor_sync(0xFFFFFFFFu, sum0, 2);
        sum1 += __shfl_xor_sync(0xFFFFFFFFu, sum1, 1);
        sum1 += __shfl_xor_sync(0xFFFFFFFFu, sum1, 2);
        l0 = l0 * e0 + sum0;
        l1 = l1 * e1 + sum1;

        #pragma unroll
        for (int nf = 0; nf < 16; nf++) {
            o[nf][0] *= e0; o[nf][1] *= e0;
            o[nf][2] *= e1; o[nf][3] *= e1;
        }
        __syncthreads();   // V visible

        // --- O += P V  (k-relabel τ: a = {c0,c2,c1,c3}; V rows 2t, 2t+1) ---
        #pragma unroll 1
        for (int kb = 0; kb < 16; kb++) {
            uint32_t a2[4] = {p[kb][0], p[kb][2], p[kb][1], p[kb][3]};
            int vr = (kb * 8 + 2 * t) * QSTR;
            #pragma unroll
            for (int nf = 0; nf < 16; nf++) {
                uint32_t bfr[2];
                bfr[0] = __float_as_uint(KVs[vr + nf * 8 + g]);
                bfr[1] = __float_as_uint(KVs[vr + QSTR + nf * 8 + g]);
                mma_tf32(o[nf], a2, bfr);
            }
        }
    }

    // --- write partials ---
    const int r0 = warp_m + frow;
    const int r1 = r0 + 8;
    #pragma unroll
    for (int nf = 0; nf < 16; nf++) {
        *(float2*)&g_pO[pbase + (size_t)r0 * HEAD + nf * 8 + fc2] =
            make_float2(o[nf][0], o[nf][1]);
        *(float2*)&g_pO[pbase + (size_t)r1 * HEAD + nf * 8 + fc2] =
            make_float2(o[nf][2], o[nf][3]);
    }
    if ((lane & 3) == 0) {
        g_pm[prow0 + r0] = m0;
        g_pl[prow0 + r0] = l0;
        g_pm[prow0 + r1] = m1;
        g_pl[prow0 + r1] = l1;
    }
}

// ---------------------------------------------------------------------------
__global__ __launch_bounds__(256) void merge_kernel(float* __restrict__ out)
{
    const int idx = blockIdx.x * 256 + threadIdx.x;
    const int row = idx >> 5;
    const int c4  = idx & 31;

    const float m0 = g_pm[row], m1 = g_pm[MROWS + row];
    const float l0 = g_pl[row], l1 = g_pl[MROWS + row];
    const float m  = fmaxf(m0, m1);
    const float a0 = __expf(m0 - m);
    const float a1 = __expf(m1 - m);
    const float inv = 1.0f / (a0 * l0 + a1 * l1);

    float4 o0 = *(const float4*)&g_pO[(size_t)row * HEAD + c4 * 4];
    float4 o1 = *(const float4*)&g_pO[(size_t)(MROWS + row) * HEAD + c4 * 4];
    float4 r;
    r.x = (a0 * o0.x + a1 * o1.x) * inv;
    r.y = (a0 * o0.y + a1 * o1.y) * inv;
    r.z = (a0 * o0.z + a1 * o1.z) * inv;
    r.w = (a0 * o0.w + a1 * o1.w) * inv;
    *(float4*)&out[(size_t)row * HEAD + c4 * 4] = r;
}

// ---------------------------------------------------------------------------
extern "C" void kernel_launch(void* const* d_in, const int* in_sizes, int n_in,
                              void* d_out, int out_size)
{
    const float* x  = (const float*)d_in[0];
    const float* Wk = (const float*)d_in[1];
    // d_in[2] = W_query: unused (reference uses key() for q too)
    const float* Wv = (const float*)d_in[3];
    float* out = (float*)d_out;

    wprep_kernel<<<1024, 256>>>(Wk, Wv);

    cudaFuncSetAttribute(proj_mma_kernel, cudaFuncAttributeMaxDynamicSharedMemorySize,
                         PROJ_SMEM);
    dim3 pgrid(128, 2);
    proj_mma_kernel<<<pgrid, 256, PROJ_SMEM>>>(x);

    cudaFuncSetAttribute(attn_partial, cudaFuncAttributeMaxDynamicSharedMemorySize,
                         ATTN_SMEM);
    attn_partial<<<256, 256, ATTN_SMEM>>>();

    merge_kernel<<<(MROWS * 32) / 256, 256>>>(out);
}

// round 12
// speedup vs baseline: 1.5207x; 1.5207x over previous
#include <cuda_runtime.h>
#include <cuda_bf16.h>
#include <stdint.h>

#define BATCH   8
#define SEQ     2048
#define EMBED   1024
#define HEAD    128
#define MROWS   16384
#define TQ      16

// Scratch — __device__ globals, no alloc.
__device__ float g_pO[2 * MROWS * HEAD];
__device__ float g_pm[2 * MROWS];
__device__ float g_pl[2 * MROWS];
// K/V projections stored bf16-split (written by proj epilogue)
__device__ __align__(16) __nv_bfloat16 g_Khi[MROWS * HEAD];
__device__ __align__(16) __nv_bfloat16 g_Klo[MROWS * HEAD];
__device__ __align__(16) __nv_bfloat16 g_Vhi[MROWS * HEAD];
__device__ __align__(16) __nv_bfloat16 g_Vlo[MROWS * HEAD];
// W transposed + bf16-split for proj
__device__ __align__(16) __nv_bfloat16 g_wt_hi[2 * HEAD * EMBED];
__device__ __align__(16) __nv_bfloat16 g_wt_lo[2 * HEAD * EMBED];

// ---------------------------------------------------------------------------
__device__ __forceinline__ uint32_t smem_u32(const void* p) {
    uint32_t a;
    asm("{ .reg .u64 t; cvta.to.shared.u64 t, %1; cvt.u32.u64 %0, t; }"
        : "=r"(a) : "l"(p));
    return a;
}
__device__ __forceinline__ void ldsm_x4(uint32_t* r, uint32_t addr) {
    asm volatile("ldmatrix.sync.aligned.m8n8.x4.shared.b16 {%0,%1,%2,%3}, [%4];"
                 : "=r"(r[0]), "=r"(r[1]), "=r"(r[2]), "=r"(r[3]) : "r"(addr));
}
__device__ __forceinline__ void ldsm_x2(uint32_t* r, uint32_t addr) {
    asm volatile("ldmatrix.sync.aligned.m8n8.x2.shared.b16 {%0,%1}, [%2];"
                 : "=r"(r[0]), "=r"(r[1]) : "r"(addr));
}
__device__ __forceinline__ void ldsm_x2t(uint32_t* r, uint32_t addr) {
    asm volatile("ldmatrix.sync.aligned.m8n8.x2.trans.shared.b16 {%0,%1}, [%2];"
                 : "=r"(r[0]), "=r"(r[1]) : "r"(addr));
}
__device__ __forceinline__ void mma_bf16(float* c, const uint32_t* a, const uint32_t* b) {
    asm volatile(
        "mma.sync.aligned.m16n8k16.row.col.f32.bf16.bf16.f32 "
        "{%0,%1,%2,%3}, {%4,%5,%6,%7}, {%8,%9}, {%0,%1,%2,%3};"
        : "+f"(c[0]), "+f"(c[1]), "+f"(c[2]), "+f"(c[3])
        : "r"(a[0]), "r"(a[1]), "r"(a[2]), "r"(a[3]), "r"(b[0]), "r"(b[1]));
}
__device__ __forceinline__ void split2(float a, float b, uint32_t& hi, uint32_t& lo) {
    __nv_bfloat162 h = __floats2bfloat162_rn(a, b);
    float2 hf = __bfloat1622float2(h);
    __nv_bfloat162 l = __floats2bfloat162_rn(a - hf.x, b - hf.y);
    hi = *(uint32_t*)&h;
    lo = *(uint32_t*)&l;
}

// ---------------------------------------------------------------------------
// W prep: transpose + bf16-split. Wk/Wv are [1024][128].
// ---------------------------------------------------------------------------
__global__ __launch_bounds__(256) void wprep_kernel(
    const float* __restrict__ Wk, const float* __restrict__ Wv)
{
    int idx = blockIdx.x * 256 + threadIdx.x;
    int n = idx & 127;
    int k = (idx >> 7) & 1023;
    int m = idx >> 17;
    float f = (m ? Wv : Wk)[k * HEAD + n];
    __nv_bfloat16 hi = __float2bfloat16(f);
    float rem = f - __bfloat162float(hi);
    __nv_bfloat16 lo = __float2bfloat16(rem);
    size_t o = (size_t)(m * HEAD + n) * EMBED + k;
    g_wt_hi[o] = hi;
    g_wt_lo[o] = lo;
}

// ---------------------------------------------------------------------------
// Projection GEMM via mma.sync bf16 (3-product split).
// CTA tile 128x128, 8 warps (2x4), warp tile 64x32, k chunked by 64.
// __launch_bounds__(256,2): 2 CTAs/SM -> single wave (256 CTAs / 296 slots)
// + cross-CTA load/MMA overlap.
// ---------------------------------------------------------------------------
#define PSTR 72
#define TILE_B (128 * PSTR * 2)
#define PROJ_SMEM (4 * TILE_B)

__global__ __launch_bounds__(256, 2) void proj_mma_kernel(const float* __restrict__ x)
{
    extern __shared__ char smem[];
    __nv_bfloat16* Ahi = (__nv_bfloat16*)(smem);
    __nv_bfloat16* Alo = (__nv_bfloat16*)(smem + TILE_B);
    __nv_bfloat16* Bhi = (__nv_bfloat16*)(smem + 2 * TILE_B);
    __nv_bfloat16* Blo = (__nv_bfloat16*)(smem + 3 * TILE_B);
    const uint32_t sAhi = smem_u32(Ahi), sAlo = smem_u32(Alo);
    const uint32_t sBhi = smem_u32(Bhi), sBlo = smem_u32(Blo);

    const int bm  = blockIdx.x;
    const int bn  = blockIdx.y;
    const int tid = threadIdx.x;
    const int wid = tid >> 5;
    const int lane = tid & 31;

    const int warp_m = (wid >> 2) * 64;
    const int warp_n = (wid & 3) * 32;

    const int r = tid >> 1;
    const int h = tid & 1;
    const float* xrow = x + (size_t)(bm * 128 + r) * EMBED;
    const __nv_bfloat16* wh = g_wt_hi + (size_t)(bn * 128 + r) * EMBED;
    const __nv_bfloat16* wl = g_wt_lo + (size_t)(bn * 128 + r) * EMBED;

    const int lg = lane >> 3, lr = lane & 7;
    const int a_row_off = lr + (lg & 1) * 8;
    const int a_col_off = (lg >> 1) * 8;
    const int b_lane = lane & 15;
    const int b_row_off = b_lane & 7;
    const int b_col_off = (b_lane >> 3) * 8;

    float acc[4][4][4] = {};

    for (int c = 0; c < 16; c++) {
        const int k0 = c * 64;
        __syncthreads();
        #pragma unroll
        for (int j = 0; j < 8; j++) {
            float4 f = *(const float4*)&xrow[k0 + h * 32 + j * 4];
            uint2 hi2, lo2;
            split2(f.x, f.y, hi2.x, lo2.x);
            split2(f.z, f.w, hi2.y, lo2.y);
            int off = r * PSTR + h * 32 + j * 4;
            *(uint2*)&Ahi[off] = hi2;
            *(uint2*)&Alo[off] = lo2;
        }
        #pragma unroll
        for (int j = 0; j < 4; j++) {
            int ks = k0 + h * 32 + j * 8;
            int off = r * PSTR + h * 32 + j * 8;
            *(uint4*)&Bhi[off] = *(const uint4*)&wh[ks];
            *(uint4*)&Blo[off] = *(const uint4*)&wl[ks];
        }
        __syncthreads();

        #pragma unroll
        for (int kk4 = 0; kk4 < 4; kk4++) {
            const int kk = kk4 * 16;
            uint32_t ah[4][4], al[4][4], bh[4][2], bl[4][2];
            #pragma unroll
            for (int mf = 0; mf < 4; mf++) {
                uint32_t eo = (uint32_t)((warp_m + mf * 16 + a_row_off) * PSTR
                                         + kk + a_col_off) * 2;
                ldsm_x4(ah[mf], sAhi + eo);
                ldsm_x4(al[mf], sAlo + eo);
            }
            #pragma unroll
            for (int nf = 0; nf < 4; nf++) {
                uint32_t eo = (uint32_t)((warp_n + nf * 8 + b_row_off) * PSTR
                                         + kk + b_col_off) * 2;
                ldsm_x2(bh[nf], sBhi + eo);
                ldsm_x2(bl[nf], sBlo + eo);
            }
            #pragma unroll
            for (int mf = 0; mf < 4; mf++)
                #pragma unroll
                for (int nf = 0; nf < 4; nf++) {
                    mma_bf16(acc[mf][nf], ah[mf], bh[nf]);
                    mma_bf16(acc[mf][nf], ah[mf], bl[nf]);
                    mma_bf16(acc[mf][nf], al[mf], bh[nf]);
                }
        }
    }

    // epilogue: write bf16 hi/lo split
    __nv_bfloat16* dhi = (bn ? g_Vhi : g_Khi) + (size_t)bm * 128 * HEAD;
    __nv_bfloat16* dlo = (bn ? g_Vlo : g_Klo) + (size_t)bm * 128 * HEAD;
    const int frow = lane >> 2;
    const int fcol = (lane & 3) * 2;
    #pragma unroll
    for (int mf = 0; mf < 4; mf++) {
        #pragma unroll
        for (int nf = 0; nf < 4; nf++) {
            int row0 = warp_m + mf * 16 + frow;
            int col  = warp_n + nf * 8 + fcol;
            uint32_t h0, l0, h1, l1;
            split2(acc[mf][nf][0], acc[mf][nf][1], h0, l0);
            split2(acc[mf][nf][2], acc[mf][nf][3], h1, l1);
            *(uint32_t*)&dhi[(size_t)row0 * HEAD + col]       = h0;
            *(uint32_t*)&dlo[(size_t)row0 * HEAD + col]       = l0;
            *(uint32_t*)&dhi[(size_t)(row0 + 8) * HEAD + col] = h1;
            *(uint32_t*)&dlo[(size_t)(row0 + 8) * HEAD + col] = l1;
        }
    }
}

// ---------------------------------------------------------------------------
// Flash-attention partial on mma.sync bf16 (3-product splits everywhere).
// BQ=BK=128, 8 warps x 16 q-rows, register-resident softmax.
// grid = 256 1-D blocks: (qi, b, half) split-K schedule, big tiles first.
// ---------------------------------------------------------------------------
#define KSTR 136     // bf16 smem row stride
#define ATILE (128 * KSTR * 2)          // 34816 bytes
#define ATTN_SMEM (4 * ATILE)           // Qhi,Qlo,KVhi,KVlo = 139264

__global__ __launch_bounds__(256, 1) void attn_partial(void)
{
    const int t    = blockIdx.x;
    const int qi   = (TQ - 1) - (t >> 4);
    const int b    = (t >> 1) & 7;
    const int half = t & 1;
    const int hm   = (qi + 1) >> 1;
    const int jbeg = half ? hm : 0;
    const int jend = half ? (qi + 1) : hm;

    const int tid  = threadIdx.x;
    const int wid  = tid >> 5;
    const int lane = tid & 31;

    const size_t prow0 = (size_t)half * MROWS + (size_t)b * SEQ + qi * 128;
    const size_t pbase = prow0 * HEAD;

    if (jbeg == jend) {
        float4 z = make_float4(0.f, 0.f, 0.f, 0.f);
        #pragma unroll
        for (int i = 0; i < 16; i++)
            *(float4*)&g_pO[pbase + (size_t)(wid * 16 + i) * HEAD + lane * 4] = z;
        if (tid < 128) { g_pm[prow0 + tid] = -1e30f; g_pl[prow0 + tid] = 0.0f; }
        return;
    }

    extern __shared__ char smc[];
    __nv_bfloat16* Qhi  = (__nv_bfloat16*)(smc);
    __nv_bfloat16* Qlo  = (__nv_bfloat16*)(smc + ATILE);
    __nv_bfloat16* KVhi = (__nv_bfloat16*)(smc + 2 * ATILE);
    __nv_bfloat16* KVlo = (__nv_bfloat16*)(smc + 3 * ATILE);
    const uint32_t sQhi = smem_u32(Qhi), sQlo = smem_u32(Qlo);
    const uint32_t sKVhi = smem_u32(KVhi), sKVlo = smem_u32(KVlo);

    const int cr = tid >> 1;
    const int ch = tid & 1;

    const size_t batch0 = (size_t)b * SEQ;

    // --- load Q tile (from K projection: q = key(x)) ---
    {
        const __nv_bfloat16* qh = g_Khi + (batch0 + qi * 128 + cr) * HEAD + ch * 64;
        const __nv_bfloat16* ql = g_Klo + (batch0 + qi * 128 + cr) * HEAD + ch * 64;
        #pragma unroll
        for (int i = 0; i < 8; i++) {
            *(uint4*)&Qhi[cr * KSTR + ch * 64 + i * 8] = *(const uint4*)&qh[i * 8];
            *(uint4*)&Qlo[cr * KSTR + ch * 64 + i * 8] = *(const uint4*)&ql[i * 8];
        }
    }

    const int lg = lane >> 3, lr = lane & 7;
    const int a_row_off = lr + (lg & 1) * 8;
    const int a_col_off = (lg >> 1) * 8;
    const int b_lane = lane & 15;
    const int b_row_off = b_lane & 7;
    const int b_col_off = (b_lane >> 3) * 8;

    const int warp_m = wid * 16;
    const int frow = lane >> 2;
    const int fc2  = (lane & 3) * 2;

    float o[16][4] = {};
    float m0 = -1e30f, m1 = -1e30f, l0 = 0.f, l1 = 0.f;
    const float sc = 0.08838834764831845f;

    for (int j = jbeg; j < jend; j++) {
        __syncthreads();
        // --- load K tile ---
        {
            const __nv_bfloat16* kh = g_Khi + (batch0 + j * 128 + cr) * HEAD + ch * 64;
            const __nv_bfloat16* kl = g_Klo + (batch0 + j * 128 + cr) * HEAD + ch * 64;
            #pragma unroll
            for (int i = 0; i < 8; i++) {
                *(uint4*)&KVhi[cr * KSTR + ch * 64 + i * 8] = *(const uint4*)&kh[i * 8];
                *(uint4*)&KVlo[cr * KSTR + ch * 64 + i * 8] = *(const uint4*)&kl[i * 8];
            }
        }
        __syncthreads();

        // --- S = Q K^T ---
        float s[16][4];
        #pragma unroll
        for (int nf = 0; nf < 16; nf++)
            #pragma unroll
            for (int c = 0; c < 4; c++) s[nf][c] = 0.f;

        #pragma unroll 1
        for (int ks = 0; ks < 8; ks++) {
            uint32_t ah[4], al[4];
            uint32_t ao = (uint32_t)((warp_m + a_row_off) * KSTR + ks * 16 + a_col_off) * 2;
            ldsm_x4(ah, sQhi + ao);
            ldsm_x4(al, sQlo + ao);
            #pragma unroll
            for (int nf = 0; nf < 16; nf++) {
                uint32_t bh[2], bl[2];
                uint32_t bo = (uint32_t)((nf * 8 + b_row_off) * KSTR + ks * 16 + b_col_off) * 2;
                ldsm_x2(bh, sKVhi + bo);
                ldsm_x2(bl, sKVlo + bo);
                mma_bf16(s[nf], ah, bh);
                mma_bf16(s[nf], ah, bl);
                mma_bf16(s[nf], al, bh);
            }
        }
        __syncthreads();

        // --- load V tile into KV (overlaps softmax) ---
        {
            const __nv_bfloat16* vh = g_Vhi + (batch0 + j * 128 + cr) * HEAD + ch * 64;
            const __nv_bfloat16* vl = g_Vlo + (batch0 + j * 128 + cr) * HEAD + ch * 64;
            #pragma unroll
            for (int i = 0; i < 8; i++) {
                *(uint4*)&KVhi[cr * KSTR + ch * 64 + i * 8] = *(const uint4*)&vh[i * 8];
                *(uint4*)&KVlo[cr * KSTR + ch * 64 + i * 8] = *(const uint4*)&vl[i * 8];
            }
        }

        // --- softmax (registers only) ---
        #pragma unroll
        for (int nf = 0; nf < 16; nf++)
            #pragma unroll
            for (int c = 0; c < 4; c++) s[nf][c] *= sc;

        if (j == qi) {
            #pragma unroll
            for (int nf = 0; nf < 16; nf++) {
                int c0 = nf * 8 + fc2;
                int r0 = warp_m + frow;
                if (c0 > r0)         s[nf][0] = -1e30f;
                if (c0 + 1 > r0)     s[nf][1] = -1e30f;
                if (c0 > r0 + 8)     s[nf][2] = -1e30f;
                if (c0 + 1 > r0 + 8) s[nf][3] = -1e30f;
            }
        }

        float mx0 = -1e30f, mx1 = -1e30f;
        #pragma unroll
        for (int nf = 0; nf < 16; nf++) {
            mx0 = fmaxf(mx0, fmaxf(s[nf][0], s[nf][1]));
            mx1 = fmaxf(mx1, fmaxf(s[nf][2], s[nf][3]));
        }
        mx0 = fmaxf(mx0, __shfl_xor_sync(0xFFFFFFFFu, mx0, 1));
        mx0 = fmaxf(mx0, __shfl_xor_sync(0xFFFFFFFFu, mx0, 2));
        mx1 = fmaxf(mx1, __shfl_xor_sync(0xFFFFFFFFu, mx1, 1));
        mx1 = fmaxf(mx1, __shfl_xor_sync(0xFFFFFFFFu, mx1, 2));

        float mn0 = fmaxf(m0, mx0);
        float mn1 = fmaxf(m1, mx1);
        float e0 = __expf(m0 - mn0);
        float e1 = __expf(m1 - mn1);
        m0 = mn0; m1 = mn1;

        uint32_t ph01[16], ph23[16], pl01[16], pl23[16];
        float sum0 = 0.f, sum1 = 0.f;
        #pragma unroll
        for (int nf = 0; nf < 16; nf++) {
            float p0 = __expf(s[nf][0] - mn0);
            float p1 = __expf(s[nf][1] - mn0);
            float p2 = __expf(s[nf][2] - mn1);
            float p3 = __expf(s[nf][3] - mn1);
            sum0 += p0 + p1;
            sum1 += p2 + p3;
            split2(p0, p1, ph01[nf], pl01[nf]);
            split2(p2, p3, ph23[nf], pl23[nf]);
        }
        sum0 += __shfl_xor_sync(0xFFFFFFFFu, sum0, 1);
        sum0 += __shfl_xor_sync(0xFFFFFFFFu, sum0, 2);
        sum1 += __shfl_xor_sync(0xFFFFFFFFu, sum1, 1);
        sum1 += __shfl_xor_sync(0xFFFFFFFFu, sum1, 2);
        l0 = l0 * e0 + sum0;
        l1 = l1 * e1 + sum1;

        #pragma unroll
        for (int nf = 0; nf < 16; nf++) {
            o[nf][0] *= e0; o[nf][1] *= e0;
            o[nf][2] *= e1; o[nf][3] *= e1;
        }
        __syncthreads();

        // --- O += P V ---
        #pragma unroll
        for (int ks = 0; ks < 8; ks++) {
            uint32_t ah[4] = {ph01[2 * ks], ph23[2 * ks], ph01[2 * ks + 1], ph23[2 * ks + 1]};
            uint32_t al[4] = {pl01[2 * ks], pl23[2 * ks], pl01[2 * ks + 1], pl23[2 * ks + 1]};
            #pragma unroll
            for (int nf = 0; nf < 16; nf++) {
                uint32_t bh[2], bl[2];
                uint32_t bo = (uint32_t)((ks * 16 + b_lane) * KSTR + nf * 8) * 2;
                ldsm_x2t(bh, sKVhi + bo);
                ldsm_x2t(bl, sKVlo + bo);
                mma_bf16(o[nf], ah, bh);
                mma_bf16(o[nf], ah, bl);
                mma_bf16(o[nf], al, bh);
            }
        }
    }

    // --- write partials ---
    const int r0 = warp_m + frow;
    const int r1 = r0 + 8;
    #pragma unroll
    for (int nf = 0; nf < 16; nf++) {
        *(float2*)&g_pO[pbase + (size_t)r0 * HEAD + nf * 8 + fc2] =
            make_float2(o[nf][0], o[nf][1]);
        *(float2*)&g_pO[pbase + (size_t)r1 * HEAD + nf * 8 + fc2] =
            make_float2(o[nf][2], o[nf][3]);
    }
    if ((lane & 3) == 0) {
        g_pm[prow0 + r0] = m0;
        g_pl[prow0 + r0] = l0;
        g_pm[prow0 + r1] = m1;
        g_pl[prow0 + r1] = l1;
    }
}

// ---------------------------------------------------------------------------
__global__ __launch_bounds__(256) void merge_kernel(float* __restrict__ out)
{
    const int idx = blockIdx.x * 256 + threadIdx.x;
    const int row = idx >> 5;
    const int c4  = idx & 31;

    const float m0 = g_pm[row], m1 = g_pm[MROWS + row];
    const float l0 = g_pl[row], l1 = g_pl[MROWS + row];
    const float m  = fmaxf(m0, m1);
    const float a0 = __expf(m0 - m);
    const float a1 = __expf(m1 - m);
    const float inv = 1.0f / (a0 * l0 + a1 * l1);

    float4 o0 = *(const float4*)&g_pO[(size_t)row * HEAD + c4 * 4];
    float4 o1 = *(const float4*)&g_pO[(size_t)(MROWS + row) * HEAD + c4 * 4];
    float4 r;
    r.x = (a0 * o0.x + a1 * o1.x) * inv;
    r.y = (a0 * o0.y + a1 * o1.y) * inv;
    r.z = (a0 * o0.z + a1 * o1.z) * inv;
    r.w = (a0 * o0.w + a1 * o1.w) * inv;
    *(float4*)&out[(size_t)row * HEAD + c4 * 4] = r;
}

// ---------------------------------------------------------------------------
extern "C" void kernel_launch(void* const* d_in, const int* in_sizes, int n_in,
                              void* d_out, int out_size)
{
    const float* x  = (const float*)d_in[0];
    const float* Wk = (const float*)d_in[1];
    // d_in[2] = W_query: unused (reference uses key() for q too)
    const float* Wv = (const float*)d_in[3];
    float* out = (float*)d_out;

    wprep_kernel<<<1024, 256>>>(Wk, Wv);

    cudaFuncSetAttribute(proj_mma_kernel, cudaFuncAttributeMaxDynamicSharedMemorySize,
                         PROJ_SMEM);
    dim3 pgrid(128, 2);
    proj_mma_kernel<<<pgrid, 256, PROJ_SMEM>>>(x);

    cudaFuncSetAttribute(attn_partial, cudaFuncAttributeMaxDynamicSharedMemorySize,
                         ATTN_SMEM);
    attn_partial<<<256, 256, ATTN_SMEM>>>();

    merge_kernel<<<(MROWS * 32) / 256, 256>>>(out);
}